// round 15
// baseline (speedup 1.0000x reference)
#include <cuda_runtime.h>
#include <cuda_fp16.h>
#include <cstdint>
#include <math.h>

#define BB 8
#define TT 8
#define NSPACE 197
#define NQ 1576
#define NK 1576
#define DIM 768
#define NHEAD 12
#define HD 64
#define MTOK 12608
#define GK 768

// ---------------- scratch ----------------
__device__ __half g_s16 [MTOK * DIM];
__device__ __half g_a16 [MTOK * DIM];
__device__ __half g_qw16[DIM * DIM];
__device__ __half g_kvw16[2 * DIM * DIM];
__device__ __half g_pw16[DIM * DIM];
__device__ __half g_q16 [MTOK * DIM];
__device__ __half g_k16 [MTOK * DIM];
__device__ __half g_vt  [MTOK * DIM];
__device__ __half g_o16 [MTOK * DIM];

__device__ __forceinline__ void mma_f16_16x8x16(float* c, const uint32_t* a, const uint32_t* b) {
    asm volatile(
        "mma.sync.aligned.m16n8k16.row.col.f32.f16.f16.f32 "
        "{%0,%1,%2,%3}, {%4,%5,%6,%7}, {%8,%9}, {%0,%1,%2,%3};"
        : "+f"(c[0]), "+f"(c[1]), "+f"(c[2]), "+f"(c[3])
        : "r"(a[0]), "r"(a[1]), "r"(a[2]), "r"(a[3]), "r"(b[0]), "r"(b[1]));
}
__device__ __forceinline__ uint32_t h2u(__half2 h) {
    return *(uint32_t*)&h;
}
__device__ __forceinline__ uint32_t ex2h2(float x, float y) {
    uint32_t p = h2u(__floats2half2_rn(x, y));
    uint32_t r;
    asm("ex2.approx.f16x2 %0, %1;" : "=r"(r) : "r"(p));
    return r;
}
__device__ __forceinline__ uint32_t smem_u32(const void* p) {
    uint32_t a;
    asm("{ .reg .u64 t; cvta.to.shared.u64 t, %1; cvt.u32.u64 %0, t; }" : "=r"(a) : "l"(p));
    return a;
}
__device__ __forceinline__ void cp_async16(uint32_t dst, const void* src, int bytes) {
    asm volatile("cp.async.cg.shared.global [%0], [%1], 16, %2;"
                 :: "r"(dst), "l"(src), "r"(bytes) : "memory");
}
#define CP_COMMIT() asm volatile("cp.async.commit_group;" ::: "memory")
#define CP_WAIT1()  asm volatile("cp.async.wait_group 1;" ::: "memory")
#define CP_WAIT2()  asm volatile("cp.async.wait_group 2;" ::: "memory")
#define LDM4(r, addr)                                                          \
    asm volatile("ldmatrix.sync.aligned.m8n8.x4.shared.b16 {%0,%1,%2,%3}, [%4];" \
        : "=r"((r)[0]), "=r"((r)[1]), "=r"((r)[2]), "=r"((r)[3]) : "r"(addr))

// ---------------- kernel 0: fp32 -> fp16 convert ----------------
__global__ void cvt16_kernel(const float* __restrict__ src, __half* __restrict__ dst, int n4) {
    int i = blockIdx.x * blockDim.x + threadIdx.x;
    if (i >= n4) return;
    float4 v = ((const float4*)src)[i];
    uint2 o;
    o.x = h2u(__floats2half2_rn(v.x, v.y));
    o.y = h2u(__floats2half2_rn(v.z, v.w));
    *(uint2*)(dst + (size_t)i * 4) = o;
}

// ---------------- kernel 1: build s (writes fp16) ----------------
__global__ void build_s_kernel(const float* __restrict__ s_x,
                               const float* __restrict__ pos) {
    int idx = blockIdx.x * blockDim.x + threadIdx.x;
    const int NV = MTOK * (DIM / 4);
    if (idx >= NV) return;
    int m  = idx / (DIM / 4);
    int c4 = idx - m * (DIM / 4);
    int b  = m / NK;
    int r  = m - b * NK;
    int t  = r / NSPACE;
    int n  = r - t * NSPACE;
    const float4 a = *(const float4*)(s_x + ((size_t)(n * (BB * TT) + b * TT + t)) * DIM + c4 * 4);
    const float4 p = *(const float4*)(pos + (size_t)r * DIM + c4 * 4);
    uint2 o;
    o.x = h2u(__floats2half2_rn(a.x + p.x, a.y + p.y));
    o.y = h2u(__floats2half2_rn(a.z + p.z, a.w + p.w));
    *(uint2*)(g_s16 + (size_t)m * DIM + c4 * 4) = o;
}

// ================= kernel 2: fp16 GEMM, cp.async 4-stage + ldmatrix =================
#define GSTAGE_B 20480
#define GEMM_SMEM (4 * GSTAGE_B)             // 81920 bytes

__device__ __forceinline__ void gemm_stage(uint32_t sbase, int s, int k0,
                                           const __half* __restrict__ A,
                                           const __half* __restrict__ W,
                                           int m0, int n0, int maxRowA, int tid) {
    int row = tid >> 1;
    int hoff = (tid & 1) * 16;
    int ra = m0 + row; if (ra > maxRowA) ra = maxRowA;
    const __half* pa = A + (size_t)ra * GK + k0 + hoff;
    uint32_t da = sbase + s * GSTAGE_B + row * 80 + hoff * 2;
    cp_async16(da,      pa,     16);
    cp_async16(da + 16, pa + 8, 16);
    const __half* pb = W + (size_t)(n0 + row) * GK + k0 + hoff;
    uint32_t db = sbase + s * GSTAGE_B + 10240 + row * 80 + hoff * 2;
    cp_async16(db,      pb,     16);
    cp_async16(db + 16, pb + 8, 16);
}

template<int MODE>
__global__ void __launch_bounds__(256, 2)
gemm_mma_kernel(const __half* __restrict__ A, const __half* __restrict__ W,
                const float* __restrict__ bias, float* __restrict__ C,
                int M, int N, float alpha) {
    extern __shared__ uint32_t gsm[];
    const uint32_t sbase = smem_u32(gsm);

    const int tid  = threadIdx.x;
    const int wid  = tid >> 5;
    const int lane = tid & 31;
    const int lg = lane >> 2;
    const int la = lane & 3;
    const int m0 = blockIdx.x * 128;
    const int n0 = blockIdx.y * 128;
    const int maxRowA = M - 1;
    const int wm = (wid & 1) * 64;
    const int wn = (wid >> 1) * 32;

    float acc[4][4][4];
#pragma unroll
    for (int i = 0; i < 4; i++)
#pragma unroll
        for (int j = 0; j < 4; j++)
#pragma unroll
            for (int k = 0; k < 4; k++) acc[i][j][k] = 0.f;

    const int r8 = lane & 7, mq = lane >> 3;
    const uint32_t aoff = (uint32_t)((wm + r8 + (mq & 1) * 8) * 80 + (mq >> 1) * 16);
    const uint32_t boff = (uint32_t)(10240 + (wn + r8 + (mq >> 1) * 8) * 80 + (mq & 1) * 16);

    gemm_stage(sbase, 0, 0,  A, W, m0, n0, maxRowA, tid);
    CP_COMMIT();
    gemm_stage(sbase, 1, 32, A, W, m0, n0, maxRowA, tid);
    CP_COMMIT();
    gemm_stage(sbase, 2, 64, A, W, m0, n0, maxRowA, tid);
    CP_COMMIT();

    for (int i = 0; i < 24; i++) {
        CP_WAIT2();
        __syncthreads();
        if (i + 3 < 24)
            gemm_stage(sbase, (i + 3) & 3, (i + 3) * 32, A, W, m0, n0, maxRowA, tid);
        CP_COMMIT();

        const uint32_t sb = sbase + (uint32_t)((i & 3) * GSTAGE_B);
        const uint32_t Ab = sb + aoff;
        const uint32_t Bb = sb + boff;
#pragma unroll
        for (int kk = 0; kk < 2; kk++) {
            uint32_t af[4][4];
#pragma unroll
            for (int mm = 0; mm < 4; mm++)
                LDM4(af[mm], Ab + mm * 1280 + kk * 32);
            uint32_t bf[4][2];
            {
                uint32_t t[4];
                LDM4(t, Bb + kk * 32);
                bf[0][0] = t[0]; bf[0][1] = t[1]; bf[1][0] = t[2]; bf[1][1] = t[3];
                LDM4(t, Bb + 1280 + kk * 32);
                bf[2][0] = t[0]; bf[2][1] = t[1]; bf[3][0] = t[2]; bf[3][1] = t[3];
            }
#pragma unroll
            for (int mm = 0; mm < 4; mm++)
#pragma unroll
                for (int nn = 0; nn < 4; nn++)
                    mma_f16_16x8x16(acc[mm][nn], af[mm], bf[nn]);
        }
    }

#pragma unroll
    for (int mm = 0; mm < 4; mm++) {
        const int row = m0 + wm + mm * 16 + lg;
#pragma unroll
        for (int nn = 0; nn < 4; nn++) {
            const int col = n0 + wn + nn * 8 + 2 * la;
            const float b0 = bias[col], b1 = bias[col + 1];
            float x0 = acc[mm][nn][0] + b0, y0 = acc[mm][nn][1] + b1;
            float x1 = acc[mm][nn][2] + b0, y1 = acc[mm][nn][3] + b1;
            if (MODE == 0) {
                if (row < M) {
                    float2 o; o.x = x0 * alpha; o.y = y0 * alpha;
                    *(float2*)(C + (size_t)row * N + col) = o;
                }
                if (row + 8 < M) {
                    float2 o; o.x = x1 * alpha; o.y = y1 * alpha;
                    *(float2*)(C + (size_t)(row + 8) * N + col) = o;
                }
            } else if (MODE == 2) {
                if (row < M)
                    *(__half2*)(g_q16 + (size_t)row * DIM + col) =
                        __floats2half2_rn(x0 * alpha, y0 * alpha);
                if (row + 8 < M)
                    *(__half2*)(g_q16 + (size_t)(row + 8) * DIM + col) =
                        __floats2half2_rn(x1 * alpha, y1 * alpha);
            } else {
                if (col < DIM) {
                    if (row < M)
                        *(__half2*)(g_k16 + (size_t)row * DIM + col) = __floats2half2_rn(x0, y0);
                    if (row + 8 < M)
                        *(__half2*)(g_k16 + (size_t)(row + 8) * DIM + col) = __floats2half2_rn(x1, y1);
                } else {
                    int vcol = col - DIM;
                    int hh = vcol >> 6, d = vcol & 63;
                    size_t base = ((size_t)hh * HD + d) * NK;
                    if (row < M) {
                        int bb = row / NK, tok = row - bb * NK;
                        size_t p = base + (size_t)bb * NHEAD * HD * NK + tok;
                        g_vt[p]      = __float2half_rn(x0);
                        g_vt[p + NK] = __float2half_rn(y0);
                    }
                    if (row + 8 < M) {
                        int r2 = row + 8;
                        int bb = r2 / NK, tok = r2 - bb * NK;
                        size_t p = base + (size_t)bb * NHEAD * HD * NK + tok;
                        g_vt[p]      = __float2half_rn(x1);
                        g_vt[p + NK] = __float2half_rn(y1);
                    }
                }
            }
        }
    }
}

// ================= kernel 3: flash attention v8 (128-token k-tiles) =================
// K tile: 128 token-rows x 72 halves (stride 36 words).
// VT tile: 72 d-rows (64 + ones + pad) x 136 halves (stride 68 words).
// Double-buffered; two 64-token halves computed per staged tile.
#define KSTR 36
#define VSTR2 68
#define QF_WORDS (8 * 4 * 132)                // 4224
#define SM_K0 QF_WORDS
#define SM_K1 (SM_K0 + 128 * KSTR)            // +4608
#define SM_T0 (SM_K1 + 128 * KSTR)
#define SM_T1 (SM_T0 + 72 * VSTR2)            // +4896
#define ATT_WORDS (SM_T1 + 72 * VSTR2)        // 23232
#define ATT_SMEM  (ATT_WORDS * 4)             // 92928 bytes
#define NT2 13                                // ceil(1576/128)
#define SMASK (-16000.0f)

__device__ __forceinline__ void stage_kvt(uint32_t sbase, int smK, int smT,
                                          const __half* __restrict__ k_base,
                                          const __half* __restrict__ vt_base,
                                          int kbase, int tid) {
    // K: 128 token-rows x 8 chunks of 16B
#pragma unroll
    for (int u = 0; u < 4; u++) {
        int unit = u * 256 + tid;            // 0..1023
        int tok = unit >> 3;
        int c   = unit & 7;
        int kr  = kbase + tok;
        int ok  = (kr < NK) ? 16 : 0;
        int kc  = (kr < NK) ? kr : (NK - 1);
        cp_async16(sbase + (uint32_t)(smK + tok * KSTR + c * 4) * 4,
                   k_base + (size_t)kc * DIM + c * 8, ok);
    }
    // VT: 64 d-rows x 16 chunks of 8 tokens (16B)
#pragma unroll
    for (int u = 0; u < 4; u++) {
        int unit = u * 256 + tid;
        int d = unit >> 4;
        int c = unit & 15;
        int t0 = kbase + c * 8;
        int valid = (NK - t0) * 2;
        int ok = valid < 0 ? 0 : (valid > 16 ? 16 : valid);
        cp_async16(sbase + (uint32_t)(smT + d * VSTR2 + c * 4) * 4,
                   vt_base + (size_t)d * NK + t0, ok);
    }
}

__global__ void __launch_bounds__(256, 2)
attn_mma_kernel() {
    extern __shared__ uint32_t smw[];
    const uint32_t sbase = smem_u32(smw);

    const int b  = blockIdx.z;
    const int h  = blockIdx.y;
    const int q0 = blockIdx.x * 128;
    const int tid  = threadIdx.x;
    const int w    = tid >> 5;
    const int lane = tid & 31;
    const int lg   = lane >> 2;
    const int la   = lane & 3;
    const int w16  = w * 16;

    const __half* k_base  = g_k16 + (size_t)b * NK * DIM + h * HD;
    const __half* vt_base = g_vt  + (size_t)(b * NHEAD + h) * HD * NK;

    const int r8 = lane & 7, seg = lane >> 3;
    const uint32_t lmoffK = (uint32_t)(((seg >> 1) * 8 + r8) * 144 + (seg & 1) * 16);
    const uint32_t lmoffV = (uint32_t)(((seg >> 1) * 8 + r8) * 272 + (seg & 1) * 16);

    // ---- init VT ones rows (row 64 = ones, 65..71 = zero), both buffers ----
    for (int i = tid; i < 8 * VSTR2; i += 256) {
        int r = i / VSTR2, c = i - r * VSTR2;
        uint32_t val = (r == 0) ? 0x3C003C00u : 0u;
        smw[SM_T0 + (64 + r) * VSTR2 + c] = val;
        smw[SM_T1 + (64 + r) * VSTR2 + c] = val;
    }

    stage_kvt(sbase, SM_K0, SM_T0, k_base, vt_base, 0, tid);
    CP_COMMIT();
    stage_kvt(sbase, SM_K1, SM_T1, k_base, vt_base, 128, tid);
    CP_COMMIT();

    // ---- stage Q tile into fragment-native layout ----
#pragma unroll
    for (int it = 0; it < 8; it++) {
        int idx = it * 256 + tid;
        int row = idx >> 4;
        int c4  = (idx & 15) * 4;
        int qr  = q0 + row; if (qr >= NQ) qr = NQ - 1;
        uint2 v = *(const uint2*)(g_q16 + (size_t)(b * NQ + qr) * DIM + h * HD + c4);
        int w_t  = row >> 4;
        int sub  = row & 15;
        int lg_t = sub & 7;
        int kk   = c4 >> 4;
        int rem  = c4 & 15;
        int la_t = (rem & 7) >> 1;
        int comp = (sub >> 3) + 2 * (rem >> 3);
        uint32_t* base = smw + (w_t * 4 + kk) * 132 + lg_t * 16 + comp;
        base[la_t * 4]       = v.x;
        base[(la_t + 1) * 4] = v.y;
    }

    float o[8][4], ol[4];
#pragma unroll
    for (int n = 0; n < 8; n++)
#pragma unroll
        for (int j = 0; j < 4; j++) o[n][j] = 0.f;
#pragma unroll
    for (int j = 0; j < 4; j++) ol[j] = 0.f;

    for (int kt = 0; kt < NT2; kt++) {
        const int bK = (kt & 1) ? SM_K1 : SM_K0;
        const int bT = (kt & 1) ? SM_T1 : SM_T0;

        CP_WAIT1();
        __syncthreads();

#pragma unroll
        for (int hf = 0; hf < 2; hf++) {
            const int kbase = kt * 128 + hf * 64;
            const uint32_t kb_lm = sbase + (uint32_t)bK * 4 + lmoffK + (uint32_t)hf * 9216;
            const uint32_t vt_lm = sbase + (uint32_t)bT * 4 + lmoffV + (uint32_t)hf * 128;

            // ---- S = Q @ K^T ----
            float s[8][4];
#pragma unroll
            for (int n = 0; n < 8; n++)
#pragma unroll
                for (int j = 0; j < 4; j++) s[n][j] = 0.f;

#pragma unroll
            for (int kk = 0; kk < 4; kk++) {
                uint4 afv = *(const uint4*)(smw + (w * 4 + kk) * 132 + lg * 16 + la * 4);
                uint32_t a[4] = { afv.x, afv.y, afv.z, afv.w };
#pragma unroll
                for (int np = 0; np < 4; np++) {
                    uint32_t t[4];
                    LDM4(t, kb_lm + np * 2304 + kk * 32);
                    mma_f16_16x8x16(s[2 * np],     a, t);
                    mma_f16_16x8x16(s[2 * np + 1], a, t + 2);
                }
            }

            // ---- mask tail tokens ----
            if (kbase + 64 > NK) {
#pragma unroll
                for (int n = 0; n < 8; n++) {
                    int col = kbase + n * 8 + 2 * la;
                    if (col     >= NK) { s[n][0] = SMASK; s[n][2] = SMASK; }
                    if (col + 1 >= NK) { s[n][1] = SMASK; s[n][3] = SMASK; }
                }
            }

            // ---- O += exp2(S) @ V ; l via ones row ----
#pragma unroll
            for (int kk = 0; kk < 4; kk++) {
                uint32_t a[4];
                a[0] = ex2h2(s[2 * kk][0],     s[2 * kk][1]);
                a[1] = ex2h2(s[2 * kk][2],     s[2 * kk][3]);
                a[2] = ex2h2(s[2 * kk + 1][0], s[2 * kk + 1][1]);
                a[3] = ex2h2(s[2 * kk + 1][2], s[2 * kk + 1][3]);
#pragma unroll
                for (int np = 0; np < 4; np++) {
                    uint32_t t[4];
                    LDM4(t, vt_lm + np * 4352 + kk * 32);
                    mma_f16_16x8x16(o[2 * np],     a, t);
                    mma_f16_16x8x16(o[2 * np + 1], a, t + 2);
                }
                const uint32_t* vb = smw + bT + (64 + lg) * VSTR2 + hf * 32 + kk * 8 + la;
                uint32_t bf[2] = { vb[0], vb[4] };
                mma_f16_16x8x16(ol, a, bf);
            }
        }

        __syncthreads();
        if (kt + 2 < NT2)
            stage_kvt(sbase, bK, bT, k_base, vt_base, (kt + 2) * 128, tid);
        CP_COMMIT();
    }

    // ---- epilogue ----
    const float l0 = __shfl_sync(0xffffffffu, ol[0], lane & ~3);
    const float l1 = __shfl_sync(0xffffffffu, ol[2], lane & ~3);
    const float inv0 = 1.f / l0, inv1 = 1.f / l1;
    const int r0 = q0 + w16 + lg;
    const int r1 = r0 + 8;
#pragma unroll
    for (int n = 0; n < 8; n++) {
        const int col = h * HD + n * 8 + 2 * la;
        if (r0 < NQ)
            *(uint32_t*)(g_o16 + (size_t)(b * NQ + r0) * DIM + col) =
                h2u(__floats2half2_rn(o[n][0] * inv0, o[n][1] * inv0));
        if (r1 < NQ)
            *(uint32_t*)(g_o16 + (size_t)(b * NQ + r1) * DIM + col) =
                h2u(__floats2half2_rn(o[n][2] * inv1, o[n][3] * inv1));
    }
}

// ---------------- launch ----------------
extern "C" void kernel_launch(void* const* d_in, const int* in_sizes, int n_in,
                              void* d_out, int out_size) {
    const float* s_x    = (const float*)d_in[0];
    const float* t_x    = (const float*)d_in[1];
    const float* pos    = (const float*)d_in[2];
    const float* q_w    = (const float*)d_in[3];
    const float* q_b    = (const float*)d_in[4];
    const float* kv_w   = (const float*)d_in[5];
    const float* kv_b   = (const float*)d_in[6];
    const float* proj_w = (const float*)d_in[7];
    const float* proj_b = (const float*)d_in[8];
    float* out = (float*)d_out;

    __half *p_s16, *p_a16, *p_qw, *p_kvw, *p_pw, *p_o16;
    cudaGetSymbolAddress((void**)&p_s16, g_s16);
    cudaGetSymbolAddress((void**)&p_a16, g_a16);
    cudaGetSymbolAddress((void**)&p_qw,  g_qw16);
    cudaGetSymbolAddress((void**)&p_kvw, g_kvw16);
    cudaGetSymbolAddress((void**)&p_pw,  g_pw16);
    cudaGetSymbolAddress((void**)&p_o16, g_o16);

    cudaFuncSetAttribute(gemm_mma_kernel<0>, cudaFuncAttributeMaxDynamicSharedMemorySize, GEMM_SMEM);
    cudaFuncSetAttribute(gemm_mma_kernel<1>, cudaFuncAttributeMaxDynamicSharedMemorySize, GEMM_SMEM);
    cudaFuncSetAttribute(gemm_mma_kernel<2>, cudaFuncAttributeMaxDynamicSharedMemorySize, GEMM_SMEM);
    cudaFuncSetAttribute(attn_mma_kernel, cudaFuncAttributeMaxDynamicSharedMemorySize, ATT_SMEM);

    const int mtiles = (MTOK + 127) / 128;   // 99

    // 0) converts
    cvt16_kernel<<<(MTOK * DIM / 4 + 255) / 256, 256>>>(t_x, p_a16, MTOK * DIM / 4);
    cvt16_kernel<<<(DIM * DIM / 4 + 255) / 256, 256>>>(q_w, p_qw, DIM * DIM / 4);
    cvt16_kernel<<<(2 * DIM * DIM / 4 + 255) / 256, 256>>>(kv_w, p_kvw, 2 * DIM * DIM / 4);
    cvt16_kernel<<<(DIM * DIM / 4 + 255) / 256, 256>>>(proj_w, p_pw, DIM * DIM / 4);
    // 1) s = gather(s_x) + pos (fp16)
    build_s_kernel<<<(MTOK * DIM / 4 + 255) / 256, 256>>>(s_x, pos);
    // 2) q16 = (t_x @ q_w^T + q_b) * 0.125 * log2(e)
    gemm_mma_kernel<2><<<dim3(mtiles, DIM / 128), 256, GEMM_SMEM>>>(
        p_a16, p_qw, q_b, nullptr, MTOK, DIM, 0.125f * 1.4426950408889634f);
    // 3) kv = s @ kv_w^T + kv_b  -> fp16 K + transposed V
    gemm_mma_kernel<1><<<dim3(mtiles, (2 * DIM) / 128), 256, GEMM_SMEM>>>(
        p_s16, p_kvw, kv_b, nullptr, MTOK, 2 * DIM, 1.0f);
    // 4) fp16 flash attention (softmax-free, 128-token tiles)
    attn_mma_kernel<<<dim3((NQ + 127) / 128, NHEAD, BB), 256, ATT_SMEM>>>();
    // 5) out = g_o @ proj_w^T + proj_b
    gemm_mma_kernel<0><<<dim3(mtiles, DIM / 128), 256, GEMM_SMEM>>>(
        p_o16, p_pw, proj_b, out, MTOK, DIM, 1.0f);
}

// round 16
// speedup vs baseline: 1.0336x; 1.0336x over previous
#include <cuda_runtime.h>
#include <cuda_fp16.h>
#include <cstdint>
#include <math.h>

#define BB 8
#define TT 8
#define NSPACE 197
#define NQ 1576
#define NK 1576
#define DIM 768
#define NHEAD 12
#define HD 64
#define MTOK 12608
#define GK 768

// ---------------- scratch ----------------
__device__ __half g_s16 [MTOK * DIM];
__device__ __half g_a16 [MTOK * DIM];
__device__ __half g_qw16[DIM * DIM];
__device__ __half g_kvw16[2 * DIM * DIM];
__device__ __half g_pw16[DIM * DIM];
__device__ __half g_q16 [MTOK * DIM];
__device__ __half g_k16 [MTOK * DIM];
__device__ __half g_vt  [MTOK * DIM];
__device__ __half g_o16 [MTOK * DIM];

__device__ __forceinline__ void mma_f16_16x8x16(float* c, const uint32_t* a, const uint32_t* b) {
    asm volatile(
        "mma.sync.aligned.m16n8k16.row.col.f32.f16.f16.f32 "
        "{%0,%1,%2,%3}, {%4,%5,%6,%7}, {%8,%9}, {%0,%1,%2,%3};"
        : "+f"(c[0]), "+f"(c[1]), "+f"(c[2]), "+f"(c[3])
        : "r"(a[0]), "r"(a[1]), "r"(a[2]), "r"(a[3]), "r"(b[0]), "r"(b[1]));
}
__device__ __forceinline__ uint32_t h2u(__half2 h) {
    return *(uint32_t*)&h;
}
__device__ __forceinline__ uint32_t ex2h2(float x, float y) {
    uint32_t p = h2u(__floats2half2_rn(x, y));
    uint32_t r;
    asm("ex2.approx.f16x2 %0, %1;" : "=r"(r) : "r"(p));
    return r;
}
__device__ __forceinline__ uint32_t smem_u32(const void* p) {
    uint32_t a;
    asm("{ .reg .u64 t; cvta.to.shared.u64 t, %1; cvt.u32.u64 %0, t; }" : "=r"(a) : "l"(p));
    return a;
}
__device__ __forceinline__ void cp_async16(uint32_t dst, const void* src, int bytes) {
    asm volatile("cp.async.cg.shared.global [%0], [%1], 16, %2;"
                 :: "r"(dst), "l"(src), "r"(bytes) : "memory");
}
#define CP_COMMIT() asm volatile("cp.async.commit_group;" ::: "memory")
#define CP_WAIT1()  asm volatile("cp.async.wait_group 1;" ::: "memory")
#define LDM4(r, addr)                                                          \
    asm volatile("ldmatrix.sync.aligned.m8n8.x4.shared.b16 {%0,%1,%2,%3}, [%4];" \
        : "=r"((r)[0]), "=r"((r)[1]), "=r"((r)[2]), "=r"((r)[3]) : "r"(addr))

// ---------------- kernel 0: fused preamble ----------------
// Region dispatch over a linear float4 index:
//  [0, N1): t_x -> g_a16      [N1, N2): build_s -> g_s16
//  [N2, N3): q_w -> g_qw16    [N3, N4): kv_w -> g_kvw16   [N4, N5): proj_w -> g_pw16
#define PRE_N1 (MTOK * DIM / 4)
#define PRE_N2 (PRE_N1 + MTOK * DIM / 4)
#define PRE_N3 (PRE_N2 + DIM * DIM / 4)
#define PRE_N4 (PRE_N3 + 2 * DIM * DIM / 4)
#define PRE_N5 (PRE_N4 + DIM * DIM / 4)

__device__ __forceinline__ void cvt_store(const float* src4, __half* dst4) {
    float4 v = *(const float4*)src4;
    uint2 o;
    o.x = h2u(__floats2half2_rn(v.x, v.y));
    o.y = h2u(__floats2half2_rn(v.z, v.w));
    *(uint2*)dst4 = o;
}

__global__ void prep_kernel(const float* __restrict__ s_x, const float* __restrict__ pos,
                            const float* __restrict__ t_x, const float* __restrict__ q_w,
                            const float* __restrict__ kv_w, const float* __restrict__ proj_w) {
    int idx = blockIdx.x * blockDim.x + threadIdx.x;
    if (idx < PRE_N1) {
        cvt_store(t_x + (size_t)idx * 4, g_a16 + (size_t)idx * 4);
    } else if (idx < PRE_N2) {
        int i = idx - PRE_N1;
        int m  = i / (DIM / 4);
        int c4 = i - m * (DIM / 4);
        int b  = m / NK;
        int r  = m - b * NK;
        int t  = r / NSPACE;
        int n  = r - t * NSPACE;
        const float4 a = *(const float4*)(s_x + ((size_t)(n * (BB * TT) + b * TT + t)) * DIM + c4 * 4);
        const float4 p = *(const float4*)(pos + (size_t)r * DIM + c4 * 4);
        uint2 o;
        o.x = h2u(__floats2half2_rn(a.x + p.x, a.y + p.y));
        o.y = h2u(__floats2half2_rn(a.z + p.z, a.w + p.w));
        *(uint2*)(g_s16 + (size_t)m * DIM + c4 * 4) = o;
    } else if (idx < PRE_N3) {
        int i = idx - PRE_N2;
        cvt_store(q_w + (size_t)i * 4, g_qw16 + (size_t)i * 4);
    } else if (idx < PRE_N4) {
        int i = idx - PRE_N3;
        cvt_store(kv_w + (size_t)i * 4, g_kvw16 + (size_t)i * 4);
    } else if (idx < PRE_N5) {
        int i = idx - PRE_N4;
        cvt_store(proj_w + (size_t)i * 4, g_pw16 + (size_t)i * 4);
    }
}

// ================= GEMM mainloop pieces (3-stage cp.async + ldmatrix) =================
#define GSTAGE_B 20480
#define GEMM_SMEM (3 * GSTAGE_B)             // 61440 bytes

__device__ __forceinline__ void gemm_stage(uint32_t sbase, int s, int k0,
                                           const __half* __restrict__ A,
                                           const __half* __restrict__ W,
                                           int m0, int n0, int maxRowA, int tid) {
    int row = tid >> 1;
    int hoff = (tid & 1) * 16;
    int ra = m0 + row; if (ra > maxRowA) ra = maxRowA;
    const __half* pa = A + (size_t)ra * GK + k0 + hoff;
    uint32_t da = sbase + s * GSTAGE_B + row * 80 + hoff * 2;
    cp_async16(da,      pa,     16);
    cp_async16(da + 16, pa + 8, 16);
    const __half* pb = W + (size_t)(n0 + row) * GK + k0 + hoff;
    uint32_t db = sbase + s * GSTAGE_B + 10240 + row * 80 + hoff * 2;
    cp_async16(db,      pb,     16);
    cp_async16(db + 16, pb + 8, 16);
}

// mainloop: fills acc[4][4][4] for warp tile (wm, wn) of block tile (m0, n0)
__device__ __forceinline__ void gemm_mainloop(uint32_t sbase,
                                              const __half* __restrict__ A,
                                              const __half* __restrict__ W,
                                              int m0, int n0, int maxRowA,
                                              int tid, uint32_t aoff, uint32_t boff,
                                              float acc[4][4][4]) {
    gemm_stage(sbase, 0, 0,  A, W, m0, n0, maxRowA, tid);
    CP_COMMIT();
    gemm_stage(sbase, 1, 32, A, W, m0, n0, maxRowA, tid);
    CP_COMMIT();

    for (int i = 0; i < 24; i++) {
        CP_WAIT1();
        __syncthreads();
        if (i + 2 < 24)
            gemm_stage(sbase, (i + 2) % 3, (i + 2) * 32, A, W, m0, n0, maxRowA, tid);
        CP_COMMIT();

        const uint32_t sb = sbase + (uint32_t)((i % 3) * GSTAGE_B);
        const uint32_t Ab = sb + aoff;
        const uint32_t Bb = sb + boff;
#pragma unroll
        for (int kk = 0; kk < 2; kk++) {
            uint32_t af[4][4];
#pragma unroll
            for (int mm = 0; mm < 4; mm++)
                LDM4(af[mm], Ab + mm * 1280 + kk * 32);
            uint32_t bf[4][2];
            {
                uint32_t t[4];
                LDM4(t, Bb + kk * 32);
                bf[0][0] = t[0]; bf[0][1] = t[1]; bf[1][0] = t[2]; bf[1][1] = t[3];
                LDM4(t, Bb + 1280 + kk * 32);
                bf[2][0] = t[0]; bf[2][1] = t[1]; bf[3][0] = t[2]; bf[3][1] = t[3];
            }
#pragma unroll
            for (int mm = 0; mm < 4; mm++)
#pragma unroll
                for (int nn = 0; nn < 4; nn++)
                    mma_f16_16x8x16(acc[mm][nn], af[mm], bf[nn]);
        }
    }
}

// ---------------- kernel 2a: merged q + kv GEMM ----------------
// blockIdx.y < 6  : q path  -> g_q16 (alpha-scaled fp16)
// blockIdx.y >= 6 : kv path -> g_k16 / g_vt split
__global__ void __launch_bounds__(256, 2)
gemm_qkv_kernel(const float* __restrict__ q_b, const float* __restrict__ kv_b,
                float alpha_q) {
    extern __shared__ uint32_t gsm[];
    const uint32_t sbase = smem_u32(gsm);

    const int tid  = threadIdx.x;
    const int wid  = tid >> 5;
    const int lane = tid & 31;
    const int lg = lane >> 2;
    const int la = lane & 3;
    const bool isQ = blockIdx.y < 6;
    const int m0 = blockIdx.x * 128;
    const int n0 = (isQ ? blockIdx.y : (blockIdx.y - 6)) * 128;
    const int maxRowA = MTOK - 1;
    const int wm = (wid & 1) * 64;
    const int wn = (wid >> 1) * 32;

    const __half* A = isQ ? g_a16 : g_s16;
    const __half* W = isQ ? g_qw16 : g_kvw16;
    const float* bias = isQ ? q_b : kv_b;

    float acc[4][4][4];
#pragma unroll
    for (int i = 0; i < 4; i++)
#pragma unroll
        for (int j = 0; j < 4; j++)
#pragma unroll
            for (int k = 0; k < 4; k++) acc[i][j][k] = 0.f;

    const int r8 = lane & 7, mq = lane >> 3;
    const uint32_t aoff = (uint32_t)((wm + r8 + (mq & 1) * 8) * 80 + (mq >> 1) * 16);
    const uint32_t boff = (uint32_t)(10240 + (wn + r8 + (mq >> 1) * 8) * 80 + (mq & 1) * 16);

    gemm_mainloop(sbase, A, W, m0, n0, maxRowA, tid, aoff, boff, acc);

#pragma unroll
    for (int mm = 0; mm < 4; mm++) {
        const int row = m0 + wm + mm * 16 + lg;
#pragma unroll
        for (int nn = 0; nn < 4; nn++) {
            const int col = n0 + wn + nn * 8 + 2 * la;
            const float b0 = bias[col], b1 = bias[col + 1];
            float x0 = acc[mm][nn][0] + b0, y0 = acc[mm][nn][1] + b1;
            float x1 = acc[mm][nn][2] + b0, y1 = acc[mm][nn][3] + b1;
            if (isQ) {
                if (row < MTOK)
                    *(__half2*)(g_q16 + (size_t)row * DIM + col) =
                        __floats2half2_rn(x0 * alpha_q, y0 * alpha_q);
                if (row + 8 < MTOK)
                    *(__half2*)(g_q16 + (size_t)(row + 8) * DIM + col) =
                        __floats2half2_rn(x1 * alpha_q, y1 * alpha_q);
            } else {
                if (col < DIM) {
                    if (row < MTOK)
                        *(__half2*)(g_k16 + (size_t)row * DIM + col) = __floats2half2_rn(x0, y0);
                    if (row + 8 < MTOK)
                        *(__half2*)(g_k16 + (size_t)(row + 8) * DIM + col) = __floats2half2_rn(x1, y1);
                } else {
                    int vcol = col - DIM;
                    int hh = vcol >> 6, d = vcol & 63;
                    size_t base = ((size_t)hh * HD + d) * NK;
                    if (row < MTOK) {
                        int bb = row / NK, tok = row - bb * NK;
                        size_t p = base + (size_t)bb * NHEAD * HD * NK + tok;
                        g_vt[p]      = __float2half_rn(x0);
                        g_vt[p + NK] = __float2half_rn(y0);
                    }
                    if (row + 8 < MTOK) {
                        int r2 = row + 8;
                        int bb = r2 / NK, tok = r2 - bb * NK;
                        size_t p = base + (size_t)bb * NHEAD * HD * NK + tok;
                        g_vt[p]      = __float2half_rn(x1);
                        g_vt[p + NK] = __float2half_rn(y1);
                    }
                }
            }
        }
    }
}

// ---------------- kernel 2b: proj GEMM (fp32 output) ----------------
__global__ void __launch_bounds__(256, 2)
gemm_proj_kernel(const float* __restrict__ bias, float* __restrict__ C) {
    extern __shared__ uint32_t gsm[];
    const uint32_t sbase = smem_u32(gsm);

    const int tid  = threadIdx.x;
    const int wid  = tid >> 5;
    const int lane = tid & 31;
    const int lg = lane >> 2;
    const int la = lane & 3;
    const int m0 = blockIdx.x * 128;
    const int n0 = blockIdx.y * 128;
    const int maxRowA = MTOK - 1;
    const int wm = (wid & 1) * 64;
    const int wn = (wid >> 1) * 32;

    float acc[4][4][4];
#pragma unroll
    for (int i = 0; i < 4; i++)
#pragma unroll
        for (int j = 0; j < 4; j++)
#pragma unroll
            for (int k = 0; k < 4; k++) acc[i][j][k] = 0.f;

    const int r8 = lane & 7, mq = lane >> 3;
    const uint32_t aoff = (uint32_t)((wm + r8 + (mq & 1) * 8) * 80 + (mq >> 1) * 16);
    const uint32_t boff = (uint32_t)(10240 + (wn + r8 + (mq >> 1) * 8) * 80 + (mq & 1) * 16);

    gemm_mainloop(sbase, g_o16, g_pw16, m0, n0, maxRowA, tid, aoff, boff, acc);

#pragma unroll
    for (int mm = 0; mm < 4; mm++) {
        const int row = m0 + wm + mm * 16 + lg;
#pragma unroll
        for (int nn = 0; nn < 4; nn++) {
            const int col = n0 + wn + nn * 8 + 2 * la;
            const float b0 = bias[col], b1 = bias[col + 1];
            if (row < MTOK) {
                float2 o; o.x = acc[mm][nn][0] + b0; o.y = acc[mm][nn][1] + b1;
                *(float2*)(C + (size_t)row * DIM + col) = o;
            }
            if (row + 8 < MTOK) {
                float2 o; o.x = acc[mm][nn][2] + b0; o.y = acc[mm][nn][3] + b1;
                *(float2*)(C + (size_t)(row + 8) * DIM + col) = o;
            }
        }
    }
}

// ================= kernel 3: flash attention (R14 config: 64-token tiles) =================
#define HSTR 36                               // words per row (72 halves, 144 B)
#define QF_WORDS (8 * 4 * 132)                // 4224
#define SM_K0 QF_WORDS
#define SM_K1 (SM_K0 + 64 * HSTR)
#define SM_T0 (SM_K1 + 64 * HSTR)
#define SM_T1 (SM_T0 + 72 * HSTR)
#define ATT_WORDS (SM_T1 + 72 * HSTR)         // 14016
#define ATT_SMEM  (ATT_WORDS * 4)             // 56064 bytes
#define NT 25
#define SMASK (-16000.0f)

__device__ __forceinline__ void stage_kvt(uint32_t sbase, int smK, int smT,
                                          const __half* __restrict__ k_base,
                                          const __half* __restrict__ vt_base,
                                          int kbase, int tid) {
#pragma unroll
    for (int u = 0; u < 2; u++) {
        int unit = u * 256 + tid;
        int tok = unit >> 3;
        int c   = unit & 7;
        int kr  = kbase + tok;
        int ok  = (kr < NK) ? 16 : 0;
        int kc  = (kr < NK) ? kr : (NK - 1);
        cp_async16(sbase + (uint32_t)(smK + tok * HSTR + c * 4) * 4,
                   k_base + (size_t)kc * DIM + c * 8, ok);
    }
#pragma unroll
    for (int u = 0; u < 2; u++) {
        int unit = u * 256 + tid;
        int d = unit >> 3;
        int c = unit & 7;
        int t0 = kbase + c * 8;
        int valid = (NK - t0) * 2;
        int ok = valid < 0 ? 0 : (valid > 16 ? 16 : valid);
        cp_async16(sbase + (uint32_t)(smT + d * HSTR + c * 4) * 4,
                   vt_base + (size_t)d * NK + t0, ok);
    }
}

__global__ void __launch_bounds__(256, 2)
attn_mma_kernel() {
    extern __shared__ uint32_t smw[];
    const uint32_t sbase = smem_u32(smw);

    const int b  = blockIdx.z;
    const int h  = blockIdx.y;
    const int q0 = blockIdx.x * 128;
    const int tid  = threadIdx.x;
    const int w    = tid >> 5;
    const int lane = tid & 31;
    const int lg   = lane >> 2;
    const int la   = lane & 3;
    const int w16  = w * 16;

    const __half* k_base  = g_k16 + (size_t)b * NK * DIM + h * HD;
    const __half* vt_base = g_vt  + (size_t)(b * NHEAD + h) * HD * NK;

    const int r8 = lane & 7, seg = lane >> 3;
    const uint32_t lmoff = (uint32_t)(((seg >> 1) * 8 + r8) * 144 + (seg & 1) * 16);

    // ---- init VT ones rows ----
    for (int i = tid; i < 8 * HSTR; i += 256) {
        int r = i / HSTR, c = i - r * HSTR;
        uint32_t val = (r == 0) ? 0x3C003C00u : 0u;
        smw[SM_T0 + (64 + r) * HSTR + c] = val;
        smw[SM_T1 + (64 + r) * HSTR + c] = val;
    }

    stage_kvt(sbase, SM_K0, SM_T0, k_base, vt_base, 0, tid);
    CP_COMMIT();
    stage_kvt(sbase, SM_K1, SM_T1, k_base, vt_base, 64, tid);
    CP_COMMIT();

    // ---- stage Q tile (fp16) into fragment-native layout ----
#pragma unroll
    for (int it = 0; it < 8; it++) {
        int idx = it * 256 + tid;
        int row = idx >> 4;
        int c4  = (idx & 15) * 4;
        int qr  = q0 + row; if (qr >= NQ) qr = NQ - 1;
        uint2 v = *(const uint2*)(g_q16 + (size_t)(b * NQ + qr) * DIM + h * HD + c4);
        int w_t  = row >> 4;
        int sub  = row & 15;
        int lg_t = sub & 7;
        int kk   = c4 >> 4;
        int rem  = c4 & 15;
        int la_t = (rem & 7) >> 1;
        int comp = (sub >> 3) + 2 * (rem >> 3);
        uint32_t* base = smw + (w_t * 4 + kk) * 132 + lg_t * 16 + comp;
        base[la_t * 4]       = v.x;
        base[(la_t + 1) * 4] = v.y;
    }

    float o[8][4], ol[4];
#pragma unroll
    for (int n = 0; n < 8; n++)
#pragma unroll
        for (int j = 0; j < 4; j++) o[n][j] = 0.f;
#pragma unroll
    for (int j = 0; j < 4; j++) ol[j] = 0.f;

    for (int kt = 0; kt < NT; kt++) {
        const int kbase = kt * 64;
        const int bK = (kt & 1) ? SM_K1 : SM_K0;
        const int bT = (kt & 1) ? SM_T1 : SM_T0;
        const uint32_t kb_lm = sbase + (uint32_t)bK * 4 + lmoff;
        const uint32_t vt_lm = sbase + (uint32_t)bT * 4 + lmoff;

        CP_WAIT1();
        __syncthreads();

        // ---- S = Q @ K^T ----
        float s[8][4];
#pragma unroll
        for (int n = 0; n < 8; n++)
#pragma unroll
            for (int j = 0; j < 4; j++) s[n][j] = 0.f;

#pragma unroll
        for (int kk = 0; kk < 4; kk++) {
            uint4 afv = *(const uint4*)(smw + (w * 4 + kk) * 132 + lg * 16 + la * 4);
            uint32_t a[4] = { afv.x, afv.y, afv.z, afv.w };
#pragma unroll
            for (int np = 0; np < 4; np++) {
                uint32_t t[4];
                LDM4(t, kb_lm + np * 2304 + kk * 32);
                mma_f16_16x8x16(s[2 * np],     a, t);
                mma_f16_16x8x16(s[2 * np + 1], a, t + 2);
            }
        }

        // ---- mask tail tokens ----
        if (kbase + 64 > NK) {
#pragma unroll
            for (int n = 0; n < 8; n++) {
                int col = kbase + n * 8 + 2 * la;
                if (col     >= NK) { s[n][0] = SMASK; s[n][2] = SMASK; }
                if (col + 1 >= NK) { s[n][1] = SMASK; s[n][3] = SMASK; }
            }
        }

        // ---- O += exp2(S) @ V ; l via ones row (d=64) ----
#pragma unroll
        for (int kk = 0; kk < 4; kk++) {
            uint32_t a[4];
            a[0] = ex2h2(s[2 * kk][0],     s[2 * kk][1]);
            a[1] = ex2h2(s[2 * kk][2],     s[2 * kk][3]);
            a[2] = ex2h2(s[2 * kk + 1][0], s[2 * kk + 1][1]);
            a[3] = ex2h2(s[2 * kk + 1][2], s[2 * kk + 1][3]);
#pragma unroll
            for (int np = 0; np < 4; np++) {
                uint32_t t[4];
                LDM4(t, vt_lm + np * 2304 + kk * 32);
                mma_f16_16x8x16(o[2 * np],     a, t);
                mma_f16_16x8x16(o[2 * np + 1], a, t + 2);
            }
            const uint32_t* vb = smw + bT + (64 + lg) * HSTR + kk * 8 + la;
            uint32_t bf[2] = { vb[0], vb[4] };
            mma_f16_16x8x16(ol, a, bf);
        }

        __syncthreads();
        if (kt + 2 < NT)
            stage_kvt(sbase, bK, bT, k_base, vt_base, (kt + 2) * 64, tid);
        CP_COMMIT();
    }

    // ---- epilogue ----
    const float l0 = __shfl_sync(0xffffffffu, ol[0], lane & ~3);
    const float l1 = __shfl_sync(0xffffffffu, ol[2], lane & ~3);
    const float inv0 = 1.f / l0, inv1 = 1.f / l1;
    const int r0 = q0 + w16 + lg;
    const int r1 = r0 + 8;
#pragma unroll
    for (int n = 0; n < 8; n++) {
        const int col = h * HD + n * 8 + 2 * la;
        if (r0 < NQ)
            *(uint32_t*)(g_o16 + (size_t)(b * NQ + r0) * DIM + col) =
                h2u(__floats2half2_rn(o[n][0] * inv0, o[n][1] * inv0));
        if (r1 < NQ)
            *(uint32_t*)(g_o16 + (size_t)(b * NQ + r1) * DIM + col) =
                h2u(__floats2half2_rn(o[n][2] * inv1, o[n][3] * inv1));
    }
}

// ---------------- launch ----------------
extern "C" void kernel_launch(void* const* d_in, const int* in_sizes, int n_in,
                              void* d_out, int out_size) {
    const float* s_x    = (const float*)d_in[0];
    const float* t_x    = (const float*)d_in[1];
    const float* pos    = (const float*)d_in[2];
    const float* q_b    = (const float*)d_in[4];
    const float* kv_b   = (const float*)d_in[6];
    const float* proj_b = (const float*)d_in[8];
    const float* q_w    = (const float*)d_in[3];
    const float* kv_w   = (const float*)d_in[5];
    const float* proj_w = (const float*)d_in[7];
    float* out = (float*)d_out;

    cudaFuncSetAttribute(gemm_qkv_kernel,  cudaFuncAttributeMaxDynamicSharedMemorySize, GEMM_SMEM);
    cudaFuncSetAttribute(gemm_proj_kernel, cudaFuncAttributeMaxDynamicSharedMemorySize, GEMM_SMEM);
    cudaFuncSetAttribute(attn_mma_kernel,  cudaFuncAttributeMaxDynamicSharedMemorySize, ATT_SMEM);

    const int mtiles = (MTOK + 127) / 128;   // 99

    // 0+1) fused preamble: converts + build_s
    prep_kernel<<<(PRE_N5 + 255) / 256, 256>>>(s_x, pos, t_x, q_w, kv_w, proj_w);
    // 2+3) merged q (y<6) + kv (y>=6) GEMM
    gemm_qkv_kernel<<<dim3(mtiles, 18), 256, GEMM_SMEM>>>(
        q_b, kv_b, 0.125f * 1.4426950408889634f);
    // 4) fp16 flash attention (softmax-free, ldmatrix frags)
    attn_mma_kernel<<<dim3((NQ + 127) / 128, NHEAD, BB), 256, ATT_SMEM>>>();
    // 5) out = g_o @ proj_w^T + proj_b
    gemm_proj_kernel<<<dim3(mtiles, DIM / 128), 256, GEMM_SMEM>>>(proj_b, out);
}